// round 8
// baseline (speedup 1.0000x reference)
#include <cuda_runtime.h>
#include <cuda_bf16.h>
#include <cstdint>

// ===========================================================================
// InnerMonologue: bf16-split GEMMs on mma.sync, 64x64 warp tiles (fragment
// reuse), CTA tile 128x256, 3-stage cp.async. Operands pre-split in gmem.
// Output: [PR (BS*P)] [OUT (BS*H)] [is_private (BS)] [usage (B)]  (all fp32)
// ===========================================================================

#define MAX_S 32768
#define MAX_WE (2048 * 256)
#define MAX_HS (32768 * 2048)
#define MAX_PR (32768 * 256)

__device__ unsigned char g_mask[MAX_S];
__device__ __nv_bfloat16 g_Wt_hi[MAX_WE];  // W_to  transposed [P][H]
__device__ __nv_bfloat16 g_Wt_lo[MAX_WE];
__device__ __nv_bfloat16 g_Wf_hi[MAX_WE];  // W_from transposed [H][P]
__device__ __nv_bfloat16 g_Wf_lo[MAX_WE];
__device__ __nv_bfloat16 g_Hh[MAX_HS];     // hidden split hi [BS][H]
__device__ __nv_bfloat16 g_Hl[MAX_HS];
__device__ __nv_bfloat16 g_PRh[MAX_PR];    // PR split hi [BS][P]
__device__ __nv_bfloat16 g_PRl[MAX_PR];

__device__ __forceinline__ uint32_t smem_u32(const void* p) {
    uint32_t a;
    asm("{ .reg .u64 t; cvta.to.shared.u64 t, %1; cvt.u32.u64 %0, t; }"
        : "=r"(a) : "l"(p));
    return a;
}
__device__ __forceinline__ void ldsm_x4(uint32_t addr, uint32_t* r) {
    asm volatile("ldmatrix.sync.aligned.m8n8.x4.shared.b16 {%0,%1,%2,%3}, [%4];"
                 : "=r"(r[0]), "=r"(r[1]), "=r"(r[2]), "=r"(r[3])
                 : "r"(addr));
}
__device__ __forceinline__ void mma_bf16(float* c, const uint32_t* a,
                                         const uint32_t* b) {
    asm volatile(
        "mma.sync.aligned.m16n8k16.row.col.f32.bf16.bf16.f32 "
        "{%0,%1,%2,%3}, {%4,%5,%6,%7}, {%8,%9}, {%0,%1,%2,%3};"
        : "+f"(c[0]), "+f"(c[1]), "+f"(c[2]), "+f"(c[3])
        : "r"(a[0]), "r"(a[1]), "r"(a[2]), "r"(a[3]), "r"(b[0]), "r"(b[1]));
}
__device__ __forceinline__ void cp16(uint32_t dst, const void* src) {
    asm volatile("cp.async.cg.shared.global [%0], [%1], 16;"
                 :: "r"(dst), "l"(src));
}
#define CP_COMMIT() asm volatile("cp.async.commit_group;" ::: "memory")
#define CP_WAIT1()  asm volatile("cp.async.wait_group 1;" ::: "memory")

__device__ __forceinline__ uint32_t pack_hi(float x, float y) {
    return (uint32_t)__bfloat16_as_ushort(__float2bfloat16_rn(x)) |
           ((uint32_t)__bfloat16_as_ushort(__float2bfloat16_rn(y)) << 16);
}
__device__ __forceinline__ uint32_t pack_lo(float x, float y) {
    float rx = x - __bfloat162float(__float2bfloat16_rn(x));
    float ry = y - __bfloat162float(__float2bfloat16_rn(y));
    return pack_hi(rx, ry);
}

// SMEM: rows of 32 bf16, stride 80B (conflict-free ldsm).
// Per stage: Ah,Al (128 rows) + Bh,Bl (256 rows) = 48KB. 3 stages = 144KB.
#define ROWB 80
#define A_T (128 * ROWB)                   // 10240
#define B_T (256 * ROWB)                   // 20480
#define STAGE_BYTES (2 * A_T + 2 * B_T)    // 49152
#define ST_OFF(st) ((st) * STAGE_BYTES)
#define SM_DYN (3 * STAGE_BYTES)           // 147456

// ===========================================================================
// GEMM: C[128,256] CTA tile; 8 warps (2x4) of 64x64; BK=32; 3-stage cp.async.
// ===========================================================================
template <bool MASKED, bool USE_WF, bool USE_PR_A, bool WRITE_SPLIT>
__global__ void __launch_bounds__(256, 1)
gemm_mma(const float* __restrict__ bias, const float* __restrict__ HS,
         float* __restrict__ OUT, int K, int Ntot, int S) {
    extern __shared__ __align__(16) char smem[];
    __shared__ unsigned char smask[128];
    __shared__ int s_cnt;

    const __nv_bfloat16* __restrict__ Ah = USE_PR_A ? g_PRh : g_Hh;
    const __nv_bfloat16* __restrict__ Al = USE_PR_A ? g_PRl : g_Hl;
    const __nv_bfloat16* __restrict__ Bh = USE_WF ? g_Wf_hi : g_Wt_hi;
    const __nv_bfloat16* __restrict__ Bl = USE_WF ? g_Wf_lo : g_Wt_lo;

    const int tid = threadIdx.x;
    const int wid = tid >> 5;
    const int lane = tid & 31;
    const int m0 = blockIdx.y * 128;
    const int n0 = blockIdx.x * 256;

    if (MASKED) {
        if (tid == 0) s_cnt = 0;
        __syncthreads();
        if (tid < 128) {
            unsigned char mm = g_mask[(m0 + tid) % S];
            smask[tid] = mm;
            if (mm) atomicAdd(&s_cnt, 1);
        }
        __syncthreads();
        if (s_cnt == 0) {  // all-public: copy HS slab (128 x 256)
            const size_t base = (size_t)m0 * Ntot + n0;
            for (int i = tid; i < 128 * 64; i += 256) {
                int r = i >> 6, c = (i & 63) << 2;
                *(float4*)&OUT[base + (size_t)r * Ntot + c] =
                    *(const float4*)&HS[base + (size_t)r * Ntot + c];
            }
            return;
        }
    }

    const uint32_t sbase = smem_u32(smem);
    const int wm = (wid >> 2) * 64;  // 2 warp rows
    const int wn = (wid & 3) * 64;   // 4 warp cols

    // cp.async: A hi/lo = 512 16B-units each (2/thread); B = 1024 (4/thread)
    auto cp_stage = [&](int s, int st) {
        const int k0 = s << 5;
        const uint32_t dA = sbase + ST_OFF(st);
        const uint32_t dB = dA + 2 * A_T;
#pragma unroll
        for (int i = 0; i < 2; i++) {
            int u = tid * 2 + i;
            int row = u >> 2, col = u & 3;
            uint32_t d = dA + row * ROWB + col * 16;
            const size_t g = (size_t)(m0 + row) * K + k0 + col * 8;
            cp16(d, Ah + g);
            cp16(d + A_T, Al + g);
        }
#pragma unroll
        for (int i = 0; i < 4; i++) {
            int u = tid * 4 + i;
            int row = u >> 2, col = u & 3;
            uint32_t d = dB + row * ROWB + col * 16;
            const size_t g = (size_t)(n0 + row) * K + k0 + col * 8;
            cp16(d, Bh + g);
            cp16(d + B_T, Bl + g);
        }
    };

    float acc[4][8][4];
#pragma unroll
    for (int mt = 0; mt < 4; mt++)
#pragma unroll
        for (int nt = 0; nt < 8; nt++)
#pragma unroll
            for (int i = 0; i < 4; i++) acc[mt][nt][i] = 0.f;

    auto compute = [&](int st) {
        const uint32_t uAh = sbase + ST_OFF(st);
        const uint32_t uAl = uAh + A_T;
        const uint32_t uBh = uAh + 2 * A_T;
        const uint32_t uBl = uBh + B_T;
        const int r8 = lane & 7;
        const int mat = lane >> 3;
#pragma unroll
        for (int ks = 0; ks < 2; ks++) {
            const int kc = ks * 16 + (mat >> 1) * 8;
            uint32_t ahf[4][4], alf[4][4];
#pragma unroll
            for (int mt = 0; mt < 4; mt++) {
                int arow = wm + mt * 16 + (mat & 1) * 8 + r8;
                uint32_t off = (uint32_t)(arow * ROWB + kc * 2);
                ldsm_x4(uAh + off, ahf[mt]);
                ldsm_x4(uAl + off, alf[mt]);
            }
#pragma unroll
            for (int g = 0; g < 4; g++) {
                int brow = wn + g * 16 + (mat & 1) * 8 + r8;
                uint32_t off = (uint32_t)(brow * ROWB + kc * 2);
                uint32_t th[4], tl[4];
                ldsm_x4(uBh + off, th);
                ldsm_x4(uBl + off, tl);
                uint32_t b0h[2] = {th[0], th[2]}, b1h[2] = {th[1], th[3]};
                uint32_t b0l[2] = {tl[0], tl[2]}, b1l[2] = {tl[1], tl[3]};
#pragma unroll
                for (int mt = 0; mt < 4; mt++) {
                    mma_bf16(acc[mt][2 * g], ahf[mt], b0h);
                    mma_bf16(acc[mt][2 * g], ahf[mt], b0l);
                    mma_bf16(acc[mt][2 * g], alf[mt], b0h);
                    mma_bf16(acc[mt][2 * g + 1], ahf[mt], b1h);
                    mma_bf16(acc[mt][2 * g + 1], ahf[mt], b1l);
                    mma_bf16(acc[mt][2 * g + 1], alf[mt], b1h);
                }
            }
        }
    };

    const int nk = K >> 5;
    cp_stage(0, 0); CP_COMMIT();
    cp_stage(1, 1); CP_COMMIT();
    int st = 0;
    for (int s = 0; s < nk; s++) {
        CP_WAIT1();
        __syncthreads();
        if (s + 2 < nk) {
            int st2 = st + 2; if (st2 >= 3) st2 -= 3;
            cp_stage(s + 2, st2);
            CP_COMMIT();
        }
        compute(st);
        if (++st == 3) st = 0;
    }

    // ---- Epilogue ----
    const int qr = lane >> 2;
    const int qc = (lane & 3) * 2;
#pragma unroll
    for (int mt = 0; mt < 4; mt++) {
        const int lr0 = wm + mt * 16 + qr;
        const int lr1 = lr0 + 8;
        const size_t rb0 = (size_t)(m0 + lr0) * Ntot;
        const size_t rb1 = (size_t)(m0 + lr1) * Ntot;
        const bool p0 = !MASKED || (smask[lr0] != 0);
        const bool p1 = !MASKED || (smask[lr1] != 0);
#pragma unroll
        for (int nt = 0; nt < 8; nt++) {
            const int col = n0 + wn + nt * 8 + qc;
            float2 b2 = *(const float2*)&bias[col];
            float2 v0, v1;
            v0.x = acc[mt][nt][0] + b2.x;
            v0.y = acc[mt][nt][1] + b2.y;
            v1.x = acc[mt][nt][2] + b2.x;
            v1.y = acc[mt][nt][3] + b2.y;
            if (WRITE_SPLIT) {
                *(uint32_t*)&g_PRh[rb0 + col] = pack_hi(v0.x, v0.y);
                *(uint32_t*)&g_PRl[rb0 + col] = pack_lo(v0.x, v0.y);
                *(uint32_t*)&g_PRh[rb1 + col] = pack_hi(v1.x, v1.y);
                *(uint32_t*)&g_PRl[rb1 + col] = pack_lo(v1.x, v1.y);
            }
            if (MASKED) {
                if (!p0) v0 = *(const float2*)&HS[rb0 + col];
                if (!p1) v1 = *(const float2*)&HS[rb1 + col];
            }
            *(float2*)&OUT[rb0 + col] = v0;
            *(float2*)&OUT[rb1 + col] = v1;
        }
    }
}

// ===========================================================================
__global__ void split_h_kernel(const float* __restrict__ src, int n) {
    int i = (blockIdx.x * blockDim.x + threadIdx.x) * 8;
    if (i >= n) return;
    float4 v0 = *(const float4*)(src + i);
    float4 v1 = *(const float4*)(src + i + 4);
    uint4 h, l;
    h.x = pack_hi(v0.x, v0.y); l.x = pack_lo(v0.x, v0.y);
    h.y = pack_hi(v0.z, v0.w); l.y = pack_lo(v0.z, v0.w);
    h.z = pack_hi(v1.x, v1.y); l.z = pack_lo(v1.x, v1.y);
    h.w = pack_hi(v1.z, v1.w); l.w = pack_lo(v1.z, v1.w);
    *(uint4*)&g_Hh[i] = h;
    *(uint4*)&g_Hl[i] = l;
}

__global__ void scan_kernel(const int* __restrict__ tok,
                            const int* __restrict__ ttid_p,
                            float* __restrict__ usage_out, int B, int S) {
    __shared__ int stok[8192];
    __shared__ int sc[256];
    const int ttid = *ttid_p;
    const int tid = threadIdx.x;
    const bool fits = (S <= 8192);
    if (fits)
        for (int i = tid; i < S; i += 256) stok[i] = tok[i];
    __syncthreads();
    const int* src = fits ? stok : tok;

    const int chunk = (S + 255) / 256;
    const int start = tid * chunk;
    const int end = min(start + chunk, S);
    int cnt = 0;
    for (int i = start; i < end; i++) cnt += (src[i] == ttid);
    sc[tid] = cnt;
    __syncthreads();
    for (int off = 1; off < 256; off <<= 1) {
        int v = (tid >= off) ? sc[tid - off] : 0;
        __syncthreads();
        sc[tid] += v;
        __syncthreads();
    }
    int run = sc[tid] - cnt;
    int ones = 0;
    for (int i = start; i < end; i++) {
        run += (src[i] == ttid);
        unsigned char m = (unsigned char)(run & 1);
        g_mask[i] = m;
        ones += m;
    }
    __syncthreads();
    sc[tid] = ones;
    __syncthreads();
    for (int off = 128; off > 0; off >>= 1) {
        if (tid < off) sc[tid] += sc[tid + off];
        __syncthreads();
    }
    if (tid < B) usage_out[tid] = (float)sc[0] / (float)S;
}

__global__ void bcast_kernel(float* __restrict__ out_mask, int BS, int S) {
    int i = blockIdx.x * blockDim.x + threadIdx.x;
    if (i < BS) out_mask[i] = (float)g_mask[i % S];
}

__global__ void conv_w_kernel(const float* __restrict__ W_to,
                              const float* __restrict__ W_from, int H, int P) {
    int idx = blockIdx.x * blockDim.x + threadIdx.x;
    if (idx >= H * P) return;
    {  // W_to [H][P] -> Wt [P][H]
        float v = W_to[idx];
        int k = idx / P, n = idx - k * P;
        __nv_bfloat16 h = __float2bfloat16_rn(v);
        g_Wt_hi[n * H + k] = h;
        g_Wt_lo[n * H + k] = __float2bfloat16_rn(v - __bfloat162float(h));
    }
    {  // W_from [P][H] -> Wf [H][P]
        float v = W_from[idx];
        int p = idx / H, hh = idx - p * H;
        __nv_bfloat16 h = __float2bfloat16_rn(v);
        g_Wf_hi[hh * P + p] = h;
        g_Wf_lo[hh * P + p] = __float2bfloat16_rn(v - __bfloat162float(h));
    }
}

// ===========================================================================
extern "C" void kernel_launch(void* const* d_in, const int* in_sizes, int n_in,
                              void* d_out, int out_size) {
    const float* hidden = (const float*)d_in[0];
    const float* W_to   = (const float*)d_in[1];
    const float* b_to   = (const float*)d_in[2];
    const float* W_from = (const float*)d_in[3];
    const float* b_from = (const float*)d_in[4];
    const int*   token  = (const int*)d_in[5];
    const int*   ttid   = (const int*)d_in[6];

    const int P  = in_sizes[2];
    const int H  = in_sizes[4];
    const int BS = in_sizes[5];
    const int B  = out_size - BS * (P + H + 1);
    const int S  = BS / B;

    float* out = (float*)d_out;
    float* out_pr    = out;
    float* out_o     = out + (size_t)BS * P;
    float* out_mask  = out_o + (size_t)BS * H;
    float* out_usage = out_mask + BS;

    cudaFuncSetAttribute(gemm_mma<false, false, false, true>,
                         cudaFuncAttributeMaxDynamicSharedMemorySize, SM_DYN);
    cudaFuncSetAttribute(gemm_mma<true, true, true, false>,
                         cudaFuncAttributeMaxDynamicSharedMemorySize, SM_DYN);

    scan_kernel<<<1, 256>>>(token, ttid, out_usage, B, S);
    bcast_kernel<<<(BS + 255) / 256, 256>>>(out_mask, BS, S);
    conv_w_kernel<<<(H * P + 255) / 256, 256>>>(W_to, W_from, H, P);
    split_h_kernel<<<(BS * H / 8 + 255) / 256, 256>>>(hidden, BS * H);

    // GEMM1: PR = HS @ W_to + b_to   (M=BS, N=P=256 -> 1 x-block, K=H)
    gemm_mma<false, false, false, true><<<dim3(P / 256, BS / 128), 256, SM_DYN>>>(
        b_to, nullptr, out_pr, H, P, S);

    // GEMM2: OUT = blend(PR @ W_from + b_from, HS)  (M=BS, N=H, K=P)
    gemm_mma<true, true, true, false><<<dim3(H / 256, BS / 128), 256, SM_DYN>>>(
        b_from, hidden, out_o, P, H, S);
}

// round 10
// speedup vs baseline: 1.4131x; 1.4131x over previous
#include <cuda_runtime.h>
#include <cuda_bf16.h>
#include <cstdint>

// ===========================================================================
// InnerMonologue: single-pass TF32 GEMMs on mma.sync.m16n8k8.
// B weights pre-transposed + pre-rounded (rna) to tf32-in-fp32; A rounded in
// registers after ldmatrix. CTA 128x128, 16 warps 32x32, 3-stage cp.async.
// Output: [PR (BS*P)] [OUT (BS*H)] [is_private (BS)] [usage (B)]  (all fp32)
// ===========================================================================

#define MAX_S 32768
#define MAX_WE (2048 * 256)

__device__ unsigned char g_mask[MAX_S];
__device__ float g_Wt[MAX_WE];  // W_to  transposed [P][H], tf32-rounded
__device__ float g_Wf[MAX_WE];  // W_from transposed [H][P], tf32-rounded

__device__ __forceinline__ uint32_t smem_u32(const void* p) {
    uint32_t a;
    asm("{ .reg .u64 t; cvta.to.shared.u64 t, %1; cvt.u32.u64 %0, t; }"
        : "=r"(a) : "l"(p));
    return a;
}
__device__ __forceinline__ void ldsm_x4(uint32_t addr, uint32_t* r) {
    asm volatile("ldmatrix.sync.aligned.m8n8.x4.shared.b16 {%0,%1,%2,%3}, [%4];"
                 : "=r"(r[0]), "=r"(r[1]), "=r"(r[2]), "=r"(r[3])
                 : "r"(addr));
}
__device__ __forceinline__ uint32_t cvt_tf32(uint32_t x) {
    uint32_t o;
    float f = __uint_as_float(x);
    asm("cvt.rna.tf32.f32 %0, %1;" : "=r"(o) : "f"(f));
    return o;
}
__device__ __forceinline__ void mma_tf32(float* c, const uint32_t* a,
                                         const uint32_t* b) {
    asm volatile(
        "mma.sync.aligned.m16n8k8.row.col.f32.tf32.tf32.f32 "
        "{%0,%1,%2,%3}, {%4,%5,%6,%7}, {%8,%9}, {%0,%1,%2,%3};"
        : "+f"(c[0]), "+f"(c[1]), "+f"(c[2]), "+f"(c[3])
        : "r"(a[0]), "r"(a[1]), "r"(a[2]), "r"(a[3]), "r"(b[0]), "r"(b[1]));
}
__device__ __forceinline__ void cp16(uint32_t dst, const void* src) {
    asm volatile("cp.async.cg.shared.global [%0], [%1], 16;"
                 :: "r"(dst), "l"(src));
}
#define CP_COMMIT() asm volatile("cp.async.commit_group;" ::: "memory")
#define CP_WAIT1()  asm volatile("cp.async.wait_group 1;" ::: "memory")

// SMEM: rows of 32 fp32 (128B data) + 16B pad = 144B stride. Row i base bank
// = 4i mod 32, so an 8-row ldmatrix touches all 32 banks once: conflict-free.
#define ROWB 144
#define TILE_B (128 * ROWB)            // 18432
#define STAGE_B (2 * TILE_B)           // 36864
#define ST_OFF(st) ((st) * STAGE_B)
#define SM_DYN (3 * STAGE_B)           // 110592

// ===========================================================================
// GEMM: C[128,128] = A[M,K]fp32 @ B[N,K]fp32(tf32)^T + bias (+mask blend).
// 512 threads, 16 warps (4x4), warp tile 32x32, BK=32, 3-stage cp.async.
// ===========================================================================
template <bool MASKED, bool USE_WF>
__global__ void __launch_bounds__(512, 1)
gemm_tf32(const float* __restrict__ A, const float* __restrict__ bias,
          const float* __restrict__ HS, float* __restrict__ OUT,
          int K, int Ntot, int S) {
    extern __shared__ __align__(16) char smem[];
    __shared__ unsigned char smask[128];
    __shared__ int s_cnt;

    const float* __restrict__ Bw = USE_WF ? g_Wf : g_Wt;

    const int tid = threadIdx.x;
    const int wid = tid >> 5;
    const int lane = tid & 31;
    const int m0 = blockIdx.y * 128;
    const int n0 = blockIdx.x * 128;

    if (MASKED) {
        if (tid == 0) s_cnt = 0;
        __syncthreads();
        if (tid < 128) {
            unsigned char mm = g_mask[(m0 + tid) % S];
            smask[tid] = mm;
            if (mm) atomicAdd(&s_cnt, 1);
        }
        __syncthreads();
        if (s_cnt == 0) {  // all-public tile: straight copy of HS slab
            const size_t base = (size_t)m0 * Ntot + n0;
            for (int i = tid; i < 128 * 32; i += 512) {
                int r = i >> 5, c = (i & 31) << 2;
                *(float4*)&OUT[base + (size_t)r * Ntot + c] =
                    *(const float4*)&HS[base + (size_t)r * Ntot + c];
            }
            return;
        }
    }

    const uint32_t sbase = smem_u32(smem);
    const int wm = (wid >> 2) * 32;
    const int wn = (wid & 3) * 32;

    // cp.async: per operand 128 rows x 8 (16B units) = 1024; 2/thread each.
    auto cp_stage = [&](int s, int st) {
        const int k0 = s << 5;
        const uint32_t dA = sbase + ST_OFF(st);
        const uint32_t dB = dA + TILE_B;
#pragma unroll
        for (int i = 0; i < 2; i++) {
            int u = tid * 2 + i;
            int row = u >> 3, col = u & 7;          // col in 16B units
            uint32_t doff = row * ROWB + col * 16;
            const size_t ga = (size_t)(m0 + row) * K + k0 + col * 4;
            const size_t gb = (size_t)(n0 + row) * K + k0 + col * 4;
            cp16(dA + doff, A + ga);
            cp16(dB + doff, Bw + gb);
        }
    };

    float acc[2][4][4];
#pragma unroll
    for (int mt = 0; mt < 2; mt++)
#pragma unroll
        for (int nt = 0; nt < 4; nt++)
#pragma unroll
            for (int i = 0; i < 4; i++) acc[mt][nt][i] = 0.f;

    auto compute = [&](int st) {
        const uint32_t uA = sbase + ST_OFF(st);
        const uint32_t uB = uA + TILE_B;
        const int r8 = lane & 7;
        const int mat = lane >> 3;  // 0..3
        // Each ldsm_x4 (b16 view of tf32) over rows (mat&1)*8 and 16B halves
        // (mat>>1) of a 32B k8-block yields exactly the m16n8k8 fragments:
        //   A: a0=(r,c) a1=(r+8,c) a2=(r,c+4) a3=(r+8,c+4)
        //   B: t0=n(0-7),k(0-3) t1=n(8-15),k(0-3) t2=n(0-7),k(4-7) t3=...
#pragma unroll
        for (int kp = 0; kp < 4; kp++) {  // four k8 steps per BK=32
            const int kb = kp * 32;       // byte offset (8 tf32 = 32B)
            uint32_t af[2][4], bf[2][4];
#pragma unroll
            for (int mt = 0; mt < 2; mt++) {
                int arow = wm + mt * 16 + (mat & 1) * 8 + r8;
                uint32_t off = (uint32_t)(arow * ROWB + kb + (mat >> 1) * 16);
                ldsm_x4(uA + off, af[mt]);
#pragma unroll
                for (int i = 0; i < 4; i++) af[mt][i] = cvt_tf32(af[mt][i]);
            }
#pragma unroll
            for (int g = 0; g < 2; g++) {
                int brow = wn + g * 16 + (mat & 1) * 8 + r8;
                uint32_t off = (uint32_t)(brow * ROWB + kb + (mat >> 1) * 16);
                ldsm_x4(uB + off, bf[g]);
            }
#pragma unroll
            for (int g = 0; g < 2; g++) {
                uint32_t b0[2] = {bf[g][0], bf[g][2]};  // n 0-7
                uint32_t b1[2] = {bf[g][1], bf[g][3]};  // n 8-15
#pragma unroll
                for (int mt = 0; mt < 2; mt++) {
                    mma_tf32(acc[mt][2 * g], af[mt], b0);
                    mma_tf32(acc[mt][2 * g + 1], af[mt], b1);
                }
            }
        }
    };

    const int nk = K >> 5;
    cp_stage(0, 0); CP_COMMIT();
    cp_stage(1, 1); CP_COMMIT();
    int st = 0;
    for (int s = 0; s < nk; s++) {
        CP_WAIT1();
        __syncthreads();
        if (s + 2 < nk) {
            int st2 = st + 2; if (st2 >= 3) st2 -= 3;
            cp_stage(s + 2, st2);
            CP_COMMIT();
        }
        compute(st);
        if (++st == 3) st = 0;
    }

    // ---- Epilogue ----
    const int qr = lane >> 2;
    const int qc = (lane & 3) * 2;
#pragma unroll
    for (int mt = 0; mt < 2; mt++) {
        const int lr0 = wm + mt * 16 + qr;
        const int lr1 = lr0 + 8;
        const size_t rb0 = (size_t)(m0 + lr0) * Ntot;
        const size_t rb1 = (size_t)(m0 + lr1) * Ntot;
        const bool p0 = !MASKED || (smask[lr0] != 0);
        const bool p1 = !MASKED || (smask[lr1] != 0);
#pragma unroll
        for (int nt = 0; nt < 4; nt++) {
            const int col = n0 + wn + nt * 8 + qc;
            float2 b2 = *(const float2*)&bias[col];
            float2 v0, v1;
            v0.x = acc[mt][nt][0] + b2.x;
            v0.y = acc[mt][nt][1] + b2.y;
            v1.x = acc[mt][nt][2] + b2.x;
            v1.y = acc[mt][nt][3] + b2.y;
            if (MASKED) {
                if (!p0) v0 = *(const float2*)&HS[rb0 + col];
                if (!p1) v1 = *(const float2*)&HS[rb1 + col];
            }
            *(float2*)&OUT[rb0 + col] = v0;
            *(float2*)&OUT[rb1 + col] = v1;
        }
    }
}

// ===========================================================================
// Mask scan, broadcast, weight transpose (+tf32 pre-round) kernels.
// ===========================================================================
__global__ void scan_kernel(const int* __restrict__ tok,
                            const int* __restrict__ ttid_p,
                            float* __restrict__ usage_out, int B, int S) {
    __shared__ int stok[8192];
    __shared__ int sc[256];
    const int ttid = *ttid_p;
    const int tid = threadIdx.x;
    const bool fits = (S <= 8192);
    if (fits)
        for (int i = tid; i < S; i += 256) stok[i] = tok[i];
    __syncthreads();
    const int* src = fits ? stok : tok;

    const int chunk = (S + 255) / 256;
    const int start = tid * chunk;
    const int end = min(start + chunk, S);
    int cnt = 0;
    for (int i = start; i < end; i++) cnt += (src[i] == ttid);
    sc[tid] = cnt;
    __syncthreads();
    for (int off = 1; off < 256; off <<= 1) {
        int v = (tid >= off) ? sc[tid - off] : 0;
        __syncthreads();
        sc[tid] += v;
        __syncthreads();
    }
    int run = sc[tid] - cnt;
    int ones = 0;
    for (int i = start; i < end; i++) {
        run += (src[i] == ttid);
        unsigned char m = (unsigned char)(run & 1);
        g_mask[i] = m;
        ones += m;
    }
    __syncthreads();
    sc[tid] = ones;
    __syncthreads();
    for (int off = 128; off > 0; off >>= 1) {
        if (tid < off) sc[tid] += sc[tid + off];
        __syncthreads();
    }
    if (tid < B) usage_out[tid] = (float)sc[0] / (float)S;
}

__global__ void bcast_kernel(float* __restrict__ out_mask, int BS, int S) {
    int i = blockIdx.x * blockDim.x + threadIdx.x;
    if (i < BS) out_mask[i] = (float)g_mask[i % S];
}

__device__ __forceinline__ float round_tf32(float v) {
    uint32_t o;
    asm("cvt.rna.tf32.f32 %0, %1;" : "=r"(o) : "f"(v));
    return __uint_as_float(o);
}

__global__ void conv_w_kernel(const float* __restrict__ W_to,
                              const float* __restrict__ W_from, int H, int P) {
    int idx = blockIdx.x * blockDim.x + threadIdx.x;
    if (idx >= H * P) return;
    {  // W_to [H][P] -> Wt [P][H], tf32-rounded
        int k = idx / P, n = idx - k * P;
        g_Wt[n * H + k] = round_tf32(W_to[idx]);
    }
    {  // W_from [P][H] -> Wf [H][P], tf32-rounded
        int p = idx / H, hh = idx - p * H;
        g_Wf[hh * P + p] = round_tf32(W_from[idx]);
    }
}

// ===========================================================================
extern "C" void kernel_launch(void* const* d_in, const int* in_sizes, int n_in,
                              void* d_out, int out_size) {
    const float* hidden = (const float*)d_in[0];
    const float* W_to   = (const float*)d_in[1];
    const float* b_to   = (const float*)d_in[2];
    const float* W_from = (const float*)d_in[3];
    const float* b_from = (const float*)d_in[4];
    const int*   token  = (const int*)d_in[5];
    const int*   ttid   = (const int*)d_in[6];

    const int P  = in_sizes[2];
    const int H  = in_sizes[4];
    const int BS = in_sizes[5];
    const int B  = out_size - BS * (P + H + 1);
    const int S  = BS / B;

    float* out = (float*)d_out;
    float* out_pr    = out;
    float* out_o     = out + (size_t)BS * P;
    float* out_mask  = out_o + (size_t)BS * H;
    float* out_usage = out_mask + BS;

    cudaFuncSetAttribute(gemm_tf32<false, false>,
                         cudaFuncAttributeMaxDynamicSharedMemorySize, SM_DYN);
    cudaFuncSetAttribute(gemm_tf32<true, true>,
                         cudaFuncAttributeMaxDynamicSharedMemorySize, SM_DYN);

    scan_kernel<<<1, 256>>>(token, ttid, out_usage, B, S);
    bcast_kernel<<<(BS + 255) / 256, 256>>>(out_mask, BS, S);
    conv_w_kernel<<<(H * P + 255) / 256, 256>>>(W_to, W_from, H, P);

    // GEMM1: PR = HS @ W_to + b_to   (M=BS, N=P, K=H)
    gemm_tf32<false, false><<<dim3(P / 128, BS / 128), 512, SM_DYN>>>(
        hidden, b_to, nullptr, out_pr, H, P, S);

    // GEMM2: OUT = blend(PR @ W_from + b_from, HS)  (M=BS, N=H, K=P)
    gemm_tf32<true, true><<<dim3(H / 128, BS / 128), 512, SM_DYN>>>(
        out_pr, b_from, hidden, out_o, P, H, S);
}